// round 5
// baseline (speedup 1.0000x reference)
#include <cuda_runtime.h>

#define B_ 32
#define H_ 3
#define M_ 2048
#define D_ 512
#define L_ 32
#define T_ 2049

#define NCHUNK 32
#define CHUNK (M_ / NCHUNK)      // 64 m per valpart block

#define KD_BLOCKS (M_ / 16 * B_) // 4096 keydot blocks (16 m per block)
#define DOT_BLOCKS 33            // t-chunks of 64 covering T=2049
#define VP_BLOCKS (NCHUNK * B_)  // 1024 valpart blocks
#define TCC_TCHUNKS 33
#define TCC_BLOCKS (TCC_TCHUNKS * 4)  // x4 b-groups of 8
#define NCORR (TCC_TCHUNKS * 2)       // 66 corr partial chunks

// Scratch
__device__ float g_keydot[B_ * M_];
__device__ float g_p[B_ * M_];
__device__ float g_dotTA[B_ * T_];
__device__ float g_w[B_ * T_];
__device__ float g_valpart[B_ * NCHUNK * D_];
__device__ float g_corr[B_ * NCORR * D_];

// ---------------------------------------------------------------------------
__global__ void u0_kernel(const int* __restrict__ query,
                          const float* __restrict__ Bemb,
                          const float* __restrict__ pos,
                          float* __restrict__ u) {
    __shared__ int sq[L_];
    int b = blockIdx.x, d = threadIdx.x;
    if (d < L_) sq[d] = query[b * L_ + d];
    __syncthreads();
    float acc = 0.f;
#pragma unroll
    for (int l = 0; l < L_; ++l)
        acc += Bemb[(size_t)sq[l] * D_ + d] * pos[l * D_ + d];
    u[b * D_ + d] = acc;
}

// ---------------------------------------------------------------------------
// K1: keydot stream blocks + dotTA GEMM blocks (heterogeneous grid)
// keydot[b,m] = key[b,hop,m,:] . u[b,:]     (pure stream, __ldcs)
// dotTA[b,t]  = TA[hop,t,:] . u[b,:]        (reads TA once)
// ---------------------------------------------------------------------------
__global__ void k1_kernel(int hop,
                          const float* __restrict__ key,
                          const float* __restrict__ TA,
                          const float* __restrict__ u) {
    int bx = blockIdx.x;
    int tid = threadIdx.x;

    if (bx < KD_BLOCKS) {
        // ---- keydot: 8 warps x 2 m each ----
        __shared__ float4 su[D_ / 4];
        int mblk = bx & 127, b = bx >> 7;
        if (tid < D_ / 4) su[tid] = ((const float4*)(u + b * D_))[tid];
        __syncthreads();

        int warp = tid >> 5, lane = tid & 31;
        int m = mblk * 16 + warp * 2;
        const float4* k0 = (const float4*)(key + ((size_t)(b * H_ + hop) * M_ + m) * D_);
        const float4* k1 = k0 + (D_ / 4);

        float acc0 = 0.f, acc1 = 0.f;
#pragma unroll
        for (int k = 0; k < 4; ++k) {
            int idx = lane + 32 * k;
            float4 a = __ldcs(k0 + idx);
            float4 c = __ldcs(k1 + idx);
            float4 uu = su[idx];
            acc0 += a.x * uu.x + a.y * uu.y + a.z * uu.z + a.w * uu.w;
            acc1 += c.x * uu.x + c.y * uu.y + c.z * uu.z + c.w * uu.w;
        }
#pragma unroll
        for (int o = 16; o; o >>= 1) {
            acc0 += __shfl_down_sync(0xffffffffu, acc0, o);
            acc1 += __shfl_down_sync(0xffffffffu, acc1, o);
        }
        if (lane == 0) {
            g_keydot[b * M_ + m]     = acc0;
            g_keydot[b * M_ + m + 1] = acc1;
        }
    } else {
        // ---- dotTA: block covers 64 t x 32 b; warp = 8 t's, lane = b ----
        __shared__ float sTA[64 * 32];      // [t][k] tile (k-chunk of 32)
        __shared__ float sU[32 * 33];       // [b][k] padded stride 33
        int blk = bx - KD_BLOCKS;
        int t0 = blk * 64;
        int warp = tid >> 5, lane = tid & 31;

        float acc[8];
#pragma unroll
        for (int i = 0; i < 8; ++i) acc[i] = 0.f;

        for (int kc = 0; kc < 16; ++kc) {
            int k0 = kc * 32;
            // load TA tile: 64 rows x 8 float4
#pragma unroll
            for (int i = tid; i < 512; i += 256) {
                int r = i >> 3, c = i & 7;
                int t = t0 + r;
                float4 v = make_float4(0.f, 0.f, 0.f, 0.f);
                if (t < T_)
                    v = *(const float4*)(TA + ((size_t)hop * T_ + t) * D_ + k0 + c * 4);
                ((float4*)sTA)[r * 8 + c] = v;
            }
            // load u tile: 32 rows x 8 float4 -> scalar stores into padded smem
            {
                int r = tid >> 3, c = tid & 7;
                float4 v = *(const float4*)(u + r * D_ + k0 + c * 4);
                float* dst = sU + r * 33 + c * 4;
                dst[0] = v.x; dst[1] = v.y; dst[2] = v.z; dst[3] = v.w;
            }
            __syncthreads();

            int tb = warp * 8;
#pragma unroll 8
            for (int k = 0; k < 32; ++k) {
                float ur = sU[lane * 33 + k];
#pragma unroll
                for (int i = 0; i < 8; ++i)
                    acc[i] += sTA[(tb + i) * 32 + k] * ur;
            }
            __syncthreads();
        }
#pragma unroll
        for (int i = 0; i < 8; ++i) {
            int t = t0 + warp * 8 + i;
            if (t < T_) g_dotTA[(size_t)lane * T_ + t] = acc[i];
        }
    }
}

// ---------------------------------------------------------------------------
// K2: logits = keydot + dotTA[rt]; softmax over M; p out; histogram w[b,t]
// grid: B blocks of 256
// ---------------------------------------------------------------------------
__global__ void k2_kernel(const int* __restrict__ rt) {
    int b = blockIdx.x, tid = threadIdx.x;
    __shared__ float red[256];
    __shared__ float sw[T_];

    for (int i = tid; i < T_; i += 256) sw[i] = 0.f;

    float v[M_ / 256];
    int   tl[M_ / 256];
    float lmax = -1e30f;
#pragma unroll
    for (int k = 0; k < M_ / 256; ++k) {
        int m = tid + 256 * k;
        tl[k] = rt[b * M_ + m];
        v[k] = g_keydot[b * M_ + m] + g_dotTA[(size_t)b * T_ + tl[k]];
        lmax = fmaxf(lmax, v[k]);
    }
    red[tid] = lmax;
    __syncthreads();
#pragma unroll
    for (int s = 128; s; s >>= 1) {
        if (tid < s) red[tid] = fmaxf(red[tid], red[tid + s]);
        __syncthreads();
    }
    lmax = red[0];
    __syncthreads();

    float sum = 0.f;
#pragma unroll
    for (int k = 0; k < M_ / 256; ++k) {
        v[k] = __expf(v[k] - lmax);
        sum += v[k];
    }
    red[tid] = sum;
    __syncthreads();
#pragma unroll
    for (int s = 128; s; s >>= 1) {
        if (tid < s) red[tid] += red[tid + s];
        __syncthreads();
    }
    float inv = 1.f / red[0];
    __syncthreads();

#pragma unroll
    for (int k = 0; k < M_ / 256; ++k) {
        int m = tid + 256 * k;
        float p = v[k] * inv;
        g_p[b * M_ + m] = p;
        atomicAdd(&sw[tl[k]], p);
    }
    __syncthreads();
    for (int i = tid; i < T_; i += 256) g_w[(size_t)b * T_ + i] = sw[i];
}

// ---------------------------------------------------------------------------
// K3: valpart stream blocks + TC-correction GEMM blocks
// valpart[b,c,d] = sum_{m in chunk} val[b,hop,m,d] * p[b,m]   (pure stream)
// corr[b,c2,d]   = sum_{t in chunk} w[b,t] * TC[hop,t,d]      (reads TC once/bg)
// ---------------------------------------------------------------------------
__global__ void k3_kernel(int hop,
                          const float* __restrict__ val,
                          const float* __restrict__ TC) {
    int bx = blockIdx.x;
    int tid = threadIdx.x;

    if (bx < VP_BLOCKS) {
        int c = bx & (NCHUNK - 1), b = bx >> 5;
        int d4 = tid & 127, grp = tid >> 7;
        __shared__ float sp[CHUNK];
        __shared__ float4 sacc[D_ / 4];

        if (tid < CHUNK) sp[tid] = g_p[b * M_ + c * CHUNK + tid];
        __syncthreads();

        const float4* vbase = (const float4*)(val + ((size_t)(b * H_ + hop) * M_ + c * CHUNK) * D_);
        float4 acc = make_float4(0.f, 0.f, 0.f, 0.f);
#pragma unroll 8
        for (int mm = grp; mm < CHUNK; mm += 2) {
            float pm = sp[mm];
            float4 vv = __ldcs(vbase + (size_t)mm * (D_ / 4) + d4);
            acc.x += vv.x * pm; acc.y += vv.y * pm;
            acc.z += vv.z * pm; acc.w += vv.w * pm;
        }
        if (grp == 1) sacc[d4] = acc;
        __syncthreads();
        if (grp == 0) {
            float4 o = sacc[d4];
            acc.x += o.x; acc.y += o.y; acc.z += o.z; acc.w += o.w;
            ((float4*)(g_valpart + ((size_t)b * NCHUNK + c) * D_))[d4] = acc;
        }
    } else {
        // tccorr: block = (tchunk of 64 t) x (bgroup of 8 b); 128 d4-lanes x 2 t-halves
        int blk = bx - VP_BLOCKS;
        int tchunk = blk % TCC_TCHUNKS;
        int bg = blk / TCC_TCHUNKS;          // 0..3
        int t0 = tchunk * 64;
        int d4 = tid & 127, tg = tid >> 7;

        __shared__ float sw2[8][64];
        for (int i = tid; i < 8 * 64; i += 256) {
            int bi = i >> 6, tt = i & 63;
            int t = t0 + tt;
            sw2[bi][tt] = (t < T_) ? g_w[(size_t)(bg * 8 + bi) * T_ + t] : 0.f;
        }
        __syncthreads();

        float4 acc[8];
#pragma unroll
        for (int i = 0; i < 8; ++i) acc[i] = make_float4(0.f, 0.f, 0.f, 0.f);

#pragma unroll 4
        for (int tt = tg * 32; tt < tg * 32 + 32; ++tt) {
            int t = t0 + tt;
            int tc_t = (t < T_) ? t : (T_ - 1);   // clamp; sw2=0 kills contribution
            float4 tc = __ldg((const float4*)(TC + ((size_t)hop * T_ + tc_t) * D_) + d4);
#pragma unroll
            for (int bi = 0; bi < 8; ++bi) {
                float pm = sw2[bi][tt];
                acc[bi].x += tc.x * pm; acc[bi].y += tc.y * pm;
                acc[bi].z += tc.z * pm; acc[bi].w += tc.w * pm;
            }
        }
        int c2 = tchunk * 2 + tg;
#pragma unroll
        for (int bi = 0; bi < 8; ++bi) {
            int b = bg * 8 + bi;
            ((float4*)(g_corr + ((size_t)b * NCORR + c2) * D_))[d4] = acc[bi];
        }
    }
}

// ---------------------------------------------------------------------------
// K4: u[b,d] += sum valparts + sum corrparts.  grid (B,4) block 128
// ---------------------------------------------------------------------------
__global__ void update_kernel(float* __restrict__ u) {
    int b = blockIdx.x;
    int d = blockIdx.y * 128 + threadIdx.x;
    float acc = u[b * D_ + d];
#pragma unroll
    for (int c = 0; c < NCHUNK; ++c)
        acc += g_valpart[((size_t)b * NCHUNK + c) * D_ + d];
#pragma unroll
    for (int c = 0; c < NCORR; ++c)
        acc += g_corr[((size_t)b * NCORR + c) * D_ + d];
    u[b * D_ + d] = acc;
}

// ---------------------------------------------------------------------------
extern "C" void kernel_launch(void* const* d_in, const int* in_sizes, int n_in,
                              void* d_out, int out_size) {
    const int*   query = (const int*)d_in[0];
    const int*   rt    = (const int*)d_in[1];
    const float* key   = (const float*)d_in[2];
    const float* val   = (const float*)d_in[3];
    const float* Bemb  = (const float*)d_in[4];
    const float* TA    = (const float*)d_in[5];
    const float* TC    = (const float*)d_in[6];
    const float* pos   = (const float*)d_in[7];
    float* u = (float*)d_out;   // [B, D]

    u0_kernel<<<B_, D_>>>(query, Bemb, pos, u);
    for (int hop = 0; hop < H_; ++hop) {
        k1_kernel<<<KD_BLOCKS + DOT_BLOCKS, 256>>>(hop, key, TA, u);
        k2_kernel<<<B_, 256>>>(rt);
        k3_kernel<<<VP_BLOCKS + TCC_BLOCKS, 256>>>(hop, val, TC);
        update_kernel<<<dim3(B_, 4), 128>>>(u);
    }
}

// round 6
// speedup vs baseline: 1.2904x; 1.2904x over previous
#include <cuda_runtime.h>

#define B_ 32
#define H_ 3
#define M_ 2048
#define D_ 512
#define L_ 32
#define T_ 2049

#define NCHUNK 32
#define CHUNK (M_ / NCHUNK)      // 64 m per valpart block

#define DOT_BLOCKS 33            // t-chunks of 64 covering T=2049
#define TCC_TCHUNKS 33
#define TCC_BLOCKS (TCC_TCHUNKS * 4)  // x4 b-groups of 8
#define NCORR (TCC_TCHUNKS * 2)       // 66 corr partial chunks

// Scratch
__device__ float g_keydot[B_ * M_];
__device__ float g_p[B_ * M_];
__device__ float g_dotTA[B_ * T_];
__device__ float g_w[B_ * T_];
__device__ float g_valpart[B_ * NCHUNK * D_];
__device__ float g_corr[B_ * NCORR * D_];

// ---------------------------------------------------------------------------
__global__ void u0_kernel(const int* __restrict__ query,
                          const float* __restrict__ Bemb,
                          const float* __restrict__ pos,
                          float* __restrict__ u) {
    __shared__ int sq[L_];
    int b = blockIdx.x, d = threadIdx.x;
    if (d < L_) sq[d] = query[b * L_ + d];
    __syncthreads();
    float acc = 0.f;
#pragma unroll
    for (int l = 0; l < L_; ++l)
        acc += Bemb[(size_t)sq[l] * D_ + d] * pos[l * D_ + d];
    u[b * D_ + d] = acc;
}

// ---------------------------------------------------------------------------
// dotTA[b,t] = TA[hop,t,:] . u[b,:]   — small GEMM, reads TA exactly once.
// grid: 33, block 256. Standalone so its registers don't hurt the streams.
// ---------------------------------------------------------------------------
__global__ void dotTA_kernel(int hop,
                             const float* __restrict__ TA,
                             const float* __restrict__ u) {
    __shared__ float sTA[64 * 32];      // [t][k] tile (k-chunk of 32)
    __shared__ float sU[32 * 33];       // [b][k] padded
    int t0 = blockIdx.x * 64;
    int tid = threadIdx.x;
    int warp = tid >> 5, lane = tid & 31;

    float acc[8];
#pragma unroll
    for (int i = 0; i < 8; ++i) acc[i] = 0.f;

    for (int kc = 0; kc < 16; ++kc) {
        int k0 = kc * 32;
#pragma unroll
        for (int i = tid; i < 512; i += 256) {
            int r = i >> 3, c = i & 7;
            int t = t0 + r;
            float4 v = make_float4(0.f, 0.f, 0.f, 0.f);
            if (t < T_)
                v = *(const float4*)(TA + ((size_t)hop * T_ + t) * D_ + k0 + c * 4);
            ((float4*)sTA)[r * 8 + c] = v;
        }
        {
            int r = tid >> 3, c = tid & 7;
            float4 v = *(const float4*)(u + r * D_ + k0 + c * 4);
            float* dst = sU + r * 33 + c * 4;
            dst[0] = v.x; dst[1] = v.y; dst[2] = v.z; dst[3] = v.w;
        }
        __syncthreads();

        int tb = warp * 8;
#pragma unroll 8
        for (int k = 0; k < 32; ++k) {
            float ur = sU[lane * 33 + k];
#pragma unroll
            for (int i = 0; i < 8; ++i)
                acc[i] += sTA[(tb + i) * 32 + k] * ur;
        }
        __syncthreads();
    }
#pragma unroll
    for (int i = 0; i < 8; ++i) {
        int t = t0 + warp * 8 + i;
        if (t < T_) g_dotTA[(size_t)lane * T_ + t] = acc[i];
    }
}

// ---------------------------------------------------------------------------
// keydot[b,m] = key[b,hop,m,:] . u[b,:]  — pure DRAM stream, __ldcs.
// grid: (M/16, B), block 256 (8 warps x 2 m each).
// ---------------------------------------------------------------------------
__global__ void __launch_bounds__(256) keydot_kernel(int hop,
                            const float* __restrict__ key,
                            const float* __restrict__ u) {
    __shared__ float4 su[D_ / 4];
    int mblk = blockIdx.x, b = blockIdx.y;
    int tid = threadIdx.x;
    if (tid < D_ / 4) su[tid] = ((const float4*)(u + b * D_))[tid];
    __syncthreads();

    int warp = tid >> 5, lane = tid & 31;
    int m = mblk * 16 + warp * 2;
    const float4* k0 = (const float4*)(key + ((size_t)(b * H_ + hop) * M_ + m) * D_);
    const float4* k1 = k0 + (D_ / 4);

    float acc0 = 0.f, acc1 = 0.f;
#pragma unroll
    for (int k = 0; k < 4; ++k) {
        int idx = lane + 32 * k;
        float4 a = __ldcs(k0 + idx);
        float4 c = __ldcs(k1 + idx);
        float4 uu = su[idx];
        acc0 += a.x * uu.x + a.y * uu.y + a.z * uu.z + a.w * uu.w;
        acc1 += c.x * uu.x + c.y * uu.y + c.z * uu.z + c.w * uu.w;
    }
#pragma unroll
    for (int o = 16; o; o >>= 1) {
        acc0 += __shfl_down_sync(0xffffffffu, acc0, o);
        acc1 += __shfl_down_sync(0xffffffffu, acc1, o);
    }
    if (lane == 0) {
        g_keydot[b * M_ + m]     = acc0;
        g_keydot[b * M_ + m + 1] = acc1;
    }
}

// ---------------------------------------------------------------------------
// k2: logits = keydot + dotTA[rt]; softmax; p out; histogram w[b,t].
// grid: B, block 256
// ---------------------------------------------------------------------------
__global__ void k2_kernel(const int* __restrict__ rt) {
    int b = blockIdx.x, tid = threadIdx.x;
    __shared__ float red[256];
    __shared__ float sw[T_];

    for (int i = tid; i < T_; i += 256) sw[i] = 0.f;

    float v[M_ / 256];
    int   tl[M_ / 256];
    float lmax = -1e30f;
#pragma unroll
    for (int k = 0; k < M_ / 256; ++k) {
        int m = tid + 256 * k;
        tl[k] = rt[b * M_ + m];
        v[k] = g_keydot[b * M_ + m] + g_dotTA[(size_t)b * T_ + tl[k]];
        lmax = fmaxf(lmax, v[k]);
    }
    red[tid] = lmax;
    __syncthreads();
#pragma unroll
    for (int s = 128; s; s >>= 1) {
        if (tid < s) red[tid] = fmaxf(red[tid], red[tid + s]);
        __syncthreads();
    }
    lmax = red[0];
    __syncthreads();

    float sum = 0.f;
#pragma unroll
    for (int k = 0; k < M_ / 256; ++k) {
        v[k] = __expf(v[k] - lmax);
        sum += v[k];
    }
    red[tid] = sum;
    __syncthreads();
#pragma unroll
    for (int s = 128; s; s >>= 1) {
        if (tid < s) red[tid] += red[tid + s];
        __syncthreads();
    }
    float inv = 1.f / red[0];
    __syncthreads();

#pragma unroll
    for (int k = 0; k < M_ / 256; ++k) {
        int m = tid + 256 * k;
        float p = v[k] * inv;
        g_p[b * M_ + m] = p;
        atomicAdd(&sw[tl[k]], p);
    }
    __syncthreads();
    for (int i = tid; i < T_; i += 256) g_w[(size_t)b * T_ + i] = sw[i];
}

// ---------------------------------------------------------------------------
// valpart[b,c,d] = sum_{m in chunk} val[b,hop,m,d] * p[b,m] — pure stream.
// grid: (NCHUNK, B), block 256
// ---------------------------------------------------------------------------
__global__ void __launch_bounds__(256) valpart_kernel(int hop,
                             const float* __restrict__ val) {
    int c = blockIdx.x, b = blockIdx.y;
    int tid = threadIdx.x;
    int d4 = tid & 127, grp = tid >> 7;
    __shared__ float sp[CHUNK];
    __shared__ float4 sacc[D_ / 4];

    if (tid < CHUNK) sp[tid] = g_p[b * M_ + c * CHUNK + tid];
    __syncthreads();

    const float4* vbase = (const float4*)(val + ((size_t)(b * H_ + hop) * M_ + c * CHUNK) * D_);
    float4 acc = make_float4(0.f, 0.f, 0.f, 0.f);
#pragma unroll 8
    for (int mm = grp; mm < CHUNK; mm += 2) {
        float pm = sp[mm];
        float4 vv = __ldcs(vbase + (size_t)mm * (D_ / 4) + d4);
        acc.x += vv.x * pm; acc.y += vv.y * pm;
        acc.z += vv.z * pm; acc.w += vv.w * pm;
    }
    if (grp == 1) sacc[d4] = acc;
    __syncthreads();
    if (grp == 0) {
        float4 o = sacc[d4];
        acc.x += o.x; acc.y += o.y; acc.z += o.z; acc.w += o.w;
        ((float4*)(g_valpart + ((size_t)b * NCHUNK + c) * D_))[d4] = acc;
    }
}

// ---------------------------------------------------------------------------
// corr[b,c2,d] = sum_{t in chunk} w[b,t] * TC[hop,t,d] — small GEMM.
// grid: 132, block 256. Standalone (fat registers OK here).
// ---------------------------------------------------------------------------
__global__ void tccorr_kernel(int hop,
                              const float* __restrict__ TC) {
    int tchunk = blockIdx.x % TCC_TCHUNKS;
    int bg = blockIdx.x / TCC_TCHUNKS;       // 0..3
    int t0 = tchunk * 64;
    int tid = threadIdx.x;
    int d4 = tid & 127, tg = tid >> 7;

    __shared__ float sw2[8][64];
    for (int i = tid; i < 8 * 64; i += 256) {
        int bi = i >> 6, tt = i & 63;
        int t = t0 + tt;
        sw2[bi][tt] = (t < T_) ? g_w[(size_t)(bg * 8 + bi) * T_ + t] : 0.f;
    }
    __syncthreads();

    float4 acc[8];
#pragma unroll
    for (int i = 0; i < 8; ++i) acc[i] = make_float4(0.f, 0.f, 0.f, 0.f);

#pragma unroll 4
    for (int tt = tg * 32; tt < tg * 32 + 32; ++tt) {
        int t = t0 + tt;
        int tc_t = (t < T_) ? t : (T_ - 1);   // clamp; sw2=0 kills contribution
        float4 tc = __ldg((const float4*)(TC + ((size_t)hop * T_ + tc_t) * D_) + d4);
#pragma unroll
        for (int bi = 0; bi < 8; ++bi) {
            float pm = sw2[bi][tt];
            acc[bi].x += tc.x * pm; acc[bi].y += tc.y * pm;
            acc[bi].z += tc.z * pm; acc[bi].w += tc.w * pm;
        }
    }
    int c2 = tchunk * 2 + tg;
#pragma unroll
    for (int bi = 0; bi < 8; ++bi) {
        int b = bg * 8 + bi;
        ((float4*)(g_corr + ((size_t)b * NCORR + c2) * D_))[d4] = acc[bi];
    }
}

// ---------------------------------------------------------------------------
// update: u[b,d] += sum valparts + sum corrparts.  grid (B,4), block 128
// ---------------------------------------------------------------------------
__global__ void update_kernel(float* __restrict__ u) {
    int b = blockIdx.x;
    int d = blockIdx.y * 128 + threadIdx.x;
    float acc = u[b * D_ + d];
#pragma unroll
    for (int c = 0; c < NCHUNK; ++c)
        acc += g_valpart[((size_t)b * NCHUNK + c) * D_ + d];
#pragma unroll
    for (int c = 0; c < NCORR; ++c)
        acc += g_corr[((size_t)b * NCORR + c) * D_ + d];
    u[b * D_ + d] = acc;
}

// ---------------------------------------------------------------------------
extern "C" void kernel_launch(void* const* d_in, const int* in_sizes, int n_in,
                              void* d_out, int out_size) {
    const int*   query = (const int*)d_in[0];
    const int*   rt    = (const int*)d_in[1];
    const float* key   = (const float*)d_in[2];
    const float* val   = (const float*)d_in[3];
    const float* Bemb  = (const float*)d_in[4];
    const float* TA    = (const float*)d_in[5];
    const float* TC    = (const float*)d_in[6];
    const float* pos   = (const float*)d_in[7];
    float* u = (float*)d_out;   // [B, D]

    u0_kernel<<<B_, D_>>>(query, Bemb, pos, u);
    for (int hop = 0; hop < H_; ++hop) {
        dotTA_kernel<<<DOT_BLOCKS, 256>>>(hop, TA, u);
        keydot_kernel<<<dim3(M_ / 16, B_), 256>>>(hop, key, u);
        k2_kernel<<<B_, 256>>>(rt);
        valpart_kernel<<<dim3(NCHUNK, B_), 256>>>(hop, val);
        tccorr_kernel<<<TCC_BLOCKS, 256>>>(hop, TC);
        update_kernel<<<dim3(B_, 4), 128>>>(u);
    }
}

// round 7
// speedup vs baseline: 1.9479x; 1.5094x over previous
#include <cuda_runtime.h>

#define B_ 32
#define H_ 3
#define M_ 2048
#define D_ 512
#define L_ 32
#define T_ 2049

#define NCHUNK 32
#define CHUNK (M_ / NCHUNK)   // 64 memories per chunk

// Scratch
__device__ float g_logits[B_ * M_];            // raw logits
__device__ float g_opart[B_ * NCHUNK * D_];    // per-chunk weighted val partials (unnormalized)
__device__ float g_cmax[B_ * NCHUNK];          // per-chunk logit max
__device__ float g_csum[B_ * NCHUNK];          // per-chunk exp-sum (rel. to chunk max)

// ---------------------------------------------------------------------------
// u0[b,d] = sum_l B_emb[query[b,l], d] * pos_enc[l, d]
// ---------------------------------------------------------------------------
__global__ void u0_kernel(const int* __restrict__ query,
                          const float* __restrict__ Bemb,
                          const float* __restrict__ pos,
                          float* __restrict__ u) {
    __shared__ int sq[L_];
    int b = blockIdx.x, d = threadIdx.x;
    if (d < L_) sq[d] = query[b * L_ + d];
    __syncthreads();
    float acc = 0.f;
#pragma unroll
    for (int l = 0; l < L_; ++l)
        acc += Bemb[(size_t)sq[l] * D_ + d] * pos[l * D_ + d];
    u[b * D_ + d] = acc;
}

// ---------------------------------------------------------------------------
// logit[b,m] = dot( key[b,hop,m,:] + TA[hop, rt[b,m], :], u[b,:] )
// grid: (M/8, B), block 256 (one warp per row m).  [R4-proven kernel]
// ---------------------------------------------------------------------------
__global__ void __launch_bounds__(256) logits_kernel(int hop,
                              const float* __restrict__ key,
                              const float* __restrict__ TA,
                              const int* __restrict__ rt,
                              const float* __restrict__ u) {
    __shared__ float4 su[D_ / 4];
    int b = blockIdx.y;
    int tid = threadIdx.x;
    if (tid < D_ / 4) su[tid] = ((const float4*)(u + b * D_))[tid];
    __syncthreads();

    int warp = tid >> 5, lane = tid & 31;
    int m = blockIdx.x * 8 + warp;
    int t = rt[b * M_ + m];

    const float4* krow = (const float4*)(key + ((size_t)(b * H_ + hop) * M_ + m) * D_);
    const float4* trow = (const float4*)(TA + ((size_t)hop * T_ + t) * D_);

    float acc = 0.f;
#pragma unroll
    for (int k = 0; k < 4; ++k) {
        int idx = lane + 32 * k;
        float4 kv = __ldcs(krow + idx);
        float4 tv = __ldg(trow + idx);
        float4 uv = su[idx];
        acc += (kv.x + tv.x) * uv.x + (kv.y + tv.y) * uv.y
             + (kv.z + tv.z) * uv.z + (kv.w + tv.w) * uv.w;
    }
#pragma unroll
    for (int o = 16; o; o >>= 1) acc += __shfl_down_sync(0xffffffffu, acc, o);
    if (lane == 0) g_logits[b * M_ + m] = acc;
}

// ---------------------------------------------------------------------------
// Online-softmax outpart: per chunk c,
//   cmax = max_{m in c} logit,  ex_m = exp(logit_m - cmax),  csum = sum ex_m
//   o[b,c,d] = sum_m ex_m * (val[b,hop,m,d] + TC[hop,rt,d])
// grid: (NCHUNK, B), block 256 (R4 outpart structure).
// ---------------------------------------------------------------------------
__global__ void __launch_bounds__(256) outpartOS_kernel(int hop,
                               const float* __restrict__ val,
                               const float* __restrict__ TC,
                               const int* __restrict__ rt) {
    int b = blockIdx.y, c = blockIdx.x;
    int tid = threadIdx.x;
    int d4 = tid & 127, grp = tid >> 7;

    __shared__ float sl[CHUNK];
    __shared__ float ex[CHUNK];
    __shared__ int   st[CHUNK];
    __shared__ float4 sacc[D_ / 4];

    if (tid < CHUNK) {
        sl[tid] = g_logits[b * M_ + c * CHUNK + tid];
        st[tid] = rt[b * M_ + c * CHUNK + tid];
    }
    __syncthreads();

    // chunk-local max (threads < CHUNK compute redundantly via smem broadcast)
    if (tid < CHUNK) {
        float cm = sl[0];
#pragma unroll
        for (int i = 1; i < CHUNK; ++i) cm = fmaxf(cm, sl[i]);
        ex[tid] = __expf(sl[tid] - cm);
        if (tid == 0) g_cmax[b * NCHUNK + c] = cm;
    }
    __syncthreads();

    // chunk exp-sum by one thread in the last warp (overlaps with main loop start)
    if (tid == 255) {
        float s = 0.f;
#pragma unroll
        for (int i = 0; i < CHUNK; ++i) s += ex[i];
        g_csum[b * NCHUNK + c] = s;
    }

    const float4* vbase  = (const float4*)(val + ((size_t)(b * H_ + hop) * M_ + c * CHUNK) * D_);
    const float4* tcbase = (const float4*)(TC + (size_t)hop * T_ * D_);

    float4 acc = make_float4(0.f, 0.f, 0.f, 0.f);
#pragma unroll 4
    for (int mm = grp; mm < CHUNK; mm += 2) {
        float pm = ex[mm];
        float4 vv = __ldcs(vbase + (size_t)mm * (D_ / 4) + d4);
        float4 tv = __ldg(tcbase + (size_t)st[mm] * (D_ / 4) + d4);
        acc.x += (vv.x + tv.x) * pm;
        acc.y += (vv.y + tv.y) * pm;
        acc.z += (vv.z + tv.z) * pm;
        acc.w += (vv.w + tv.w) * pm;
    }

    if (grp == 1) sacc[d4] = acc;
    __syncthreads();
    if (grp == 0) {
        float4 o = sacc[d4];
        acc.x += o.x; acc.y += o.y; acc.z += o.z; acc.w += o.w;
        ((float4*)(g_opart + ((size_t)b * NCHUNK + c) * D_))[d4] = acc;
    }
}

// ---------------------------------------------------------------------------
// Combine: gmax = max_c cmax; Z = sum_c csum_c * exp(cmax_c - gmax);
//          u[b,d] += ( sum_c o[b,c,d] * exp(cmax_c - gmax) ) / Z
// grid: B, block 256 (2 d's per thread).
// ---------------------------------------------------------------------------
__global__ void combine_kernel(float* __restrict__ u) {
    int b = blockIdx.x, tid = threadIdx.x;
    __shared__ float ecf[NCHUNK];
    __shared__ float sgm, sinvZ;

    if (tid == 0) {
        float gm = g_cmax[b * NCHUNK];
#pragma unroll
        for (int i = 1; i < NCHUNK; ++i) gm = fmaxf(gm, g_cmax[b * NCHUNK + i]);
        sgm = gm;
    }
    __syncthreads();
    if (tid < NCHUNK) ecf[tid] = __expf(g_cmax[b * NCHUNK + tid] - sgm);
    __syncthreads();
    if (tid == 0) {
        float Z = 0.f;
#pragma unroll
        for (int i = 0; i < NCHUNK; ++i) Z += g_csum[b * NCHUNK + i] * ecf[i];
        sinvZ = 1.f / Z;
    }
    __syncthreads();
    float invZ = sinvZ;

#pragma unroll
    for (int r = 0; r < 2; ++r) {
        int d = tid + 256 * r;
        float acc = 0.f;
#pragma unroll
        for (int c = 0; c < NCHUNK; ++c)
            acc += g_opart[((size_t)b * NCHUNK + c) * D_ + d] * ecf[c];
        u[b * D_ + d] += acc * invZ;
    }
}

// ---------------------------------------------------------------------------
extern "C" void kernel_launch(void* const* d_in, const int* in_sizes, int n_in,
                              void* d_out, int out_size) {
    const int*   query = (const int*)d_in[0];
    const int*   rt    = (const int*)d_in[1];
    const float* key   = (const float*)d_in[2];
    const float* val   = (const float*)d_in[3];
    const float* Bemb  = (const float*)d_in[4];
    const float* TA    = (const float*)d_in[5];
    const float* TC    = (const float*)d_in[6];
    const float* pos   = (const float*)d_in[7];
    float* u = (float*)d_out;   // [B, D]

    u0_kernel<<<B_, D_>>>(query, Bemb, pos, u);
    for (int hop = 0; hop < H_; ++hop) {
        logits_kernel<<<dim3(M_ / 8, B_), 256>>>(hop, key, TA, rt, u);
        outpartOS_kernel<<<dim3(NCHUNK, B_), 256>>>(hop, val, TC, rt);
        combine_kernel<<<B_, 256>>>(u);
    }
}